// round 1
// baseline (speedup 1.0000x reference)
#include <cuda_runtime.h>

// CNF_plain: z[B,8], t scalar; MLP 9->128->128->8 with tanh; outputs
// dz_dt [B,8] and dlogp = -trace(J) [B,1], packed as [B*8 dz | B dlogp].
//
// Key identity: trace = s1^T E s2 with E = W2 .* (W1[:D,:]^T W3^T),
// s1 = 1-h1^2, s2 = 1-h2^2.  E precomputed per launch by prep_E.

#define Hh 128
#define Dd 8
#define NW 16          // warps per block
#define NS 4           // samples per warp per group
#define THREADS (NW * 32)
#define NBLK 152

// E in lane-permuted layout: p(i,j) = i*128 + (j&31)*4 + (j>>5)
__device__ float g_Ep[Hh * Hh];

__global__ void prep_E(const float* __restrict__ W1,
                       const float* __restrict__ W2,
                       const float* __restrict__ W3) {
    int idx = blockIdx.x * blockDim.x + threadIdx.x;   // 0..16383
    if (idx >= Hh * Hh) return;
    int i = idx >> 7, j = idx & 127;
    float c = 0.f;
#pragma unroll
    for (int d = 0; d < Dd; d++)
        c = fmaf(W1[d * Hh + i], W3[j * Dd + d], c);
    g_Ep[(i << 7) + ((j & 31) << 2) + (j >> 5)] = W2[i * Hh + j] * c;
}

// smem layout (floats):
//  hs        : NW*NS*128 float2 = 16384 floats
//  W2s       : 16384 (permuted)
//  Es        : 16384 (already permuted in g_Ep)
//  W1s       : 9*128 (permuted)
//  W3s       : 128*8
//  b1s,b2s   : 128 each
//  b3s       : 8
#define SMEM_FLOATS (16384 * 3 + 9 * 128 + 128 * 8 + 128 + 128 + 8)
#define SMEM_BYTES (SMEM_FLOATS * 4)

__global__ __launch_bounds__(THREADS, 1)
void cnf_main(const float* __restrict__ z, const float* __restrict__ tptr,
              const float* __restrict__ W1, const float* __restrict__ b1,
              const float* __restrict__ W2, const float* __restrict__ b2,
              const float* __restrict__ W3, const float* __restrict__ b3,
              float* __restrict__ out, int B) {
    extern __shared__ float smem[];
    float2* hs = (float2*)smem;                // [NW][NS][128]
    float* W2s = smem + 16384;
    float* Es  = W2s + 16384;
    float* W1s = Es + 16384;
    float* W3s = W1s + 9 * Hh;
    float* b1s = W3s + Hh * Dd;
    float* b2s = b1s + Hh;
    float* b3s = b2s + Hh;

    // ---- stage weights into SMEM ----
    for (int idx = threadIdx.x; idx < Hh * Hh; idx += THREADS) {
        int i = idx >> 7, j = idx & 127;
        int p = (i << 7) + ((j & 31) << 2) + (j >> 5);
        W2s[p]  = W2[idx];
        Es[idx] = g_Ep[idx];                   // already permuted
    }
    for (int idx = threadIdx.x; idx < 9 * Hh; idx += THREADS) {
        int i = idx >> 7, j = idx & 127;
        W1s[(i << 7) + ((j & 31) << 2) + (j >> 5)] = W1[idx];
    }
    for (int idx = threadIdx.x; idx < Hh * Dd; idx += THREADS)
        W3s[idx] = W3[idx];
    if (threadIdx.x < Hh) {
        b1s[threadIdx.x] = b1[threadIdx.x];
        b2s[threadIdx.x] = b2[threadIdx.x];
    }
    if (threadIdx.x < Dd) b3s[threadIdx.x] = b3[threadIdx.x];
    __syncthreads();

    const int wid = threadIdx.x >> 5;
    const int lane = threadIdx.x & 31;
    float2* myhs = hs + (wid * NS) * Hh;       // [NS][128]
    const float t = tptr[0];

    const int nGroups = B / NS;
    const int warpGlobal = blockIdx.x * NW + wid;
    const int totalWarps = gridDim.x * NW;

    for (int g = warpGlobal; g < nGroups; g += totalWarps) {
        const int s0 = g * NS;

        // ---- phase A: layer 1 (9 -> 128) ----
        float zreg[NS];
#pragma unroll
        for (int s = 0; s < NS; s++)
            zreg[s] = (lane < Dd) ? z[(size_t)(s0 + s) * Dd + lane] : t;

        float a[NS][4];
#pragma unroll
        for (int s = 0; s < NS; s++)
#pragma unroll
            for (int k = 0; k < 4; k++)
                a[s][k] = b1s[lane + 32 * k];

#pragma unroll
        for (int i = 0; i < 9; i++) {
            float4 w = *(const float4*)&W1s[(i << 7) + (lane << 2)];
#pragma unroll
            for (int s = 0; s < NS; s++) {
                float xi = __shfl_sync(0xffffffffu, zreg[s], i);
                a[s][0] = fmaf(xi, w.x, a[s][0]);
                a[s][1] = fmaf(xi, w.y, a[s][1]);
                a[s][2] = fmaf(xi, w.z, a[s][2]);
                a[s][3] = fmaf(xi, w.w, a[s][3]);
            }
        }

        __syncwarp();
#pragma unroll
        for (int s = 0; s < NS; s++)
#pragma unroll
            for (int k = 0; k < 4; k++) {
                float h = tanhf(a[s][k]);
                myhs[s * Hh + lane + 32 * k] = make_float2(h, 1.0f - h * h);
            }
        __syncwarp();

        // ---- phase B: fused GEMVs  b = h1@W2+b2,  r = s1@E ----
        float bacc[NS][4], racc[NS][4];
#pragma unroll
        for (int s = 0; s < NS; s++)
#pragma unroll
            for (int k = 0; k < 4; k++) {
                bacc[s][k] = b2s[lane + 32 * k];
                racc[s][k] = 0.f;
            }

#pragma unroll 4
        for (int i = 0; i < Hh; i++) {
            float4 w = *(const float4*)&W2s[(i << 7) + (lane << 2)];
            float4 e = *(const float4*)&Es[(i << 7) + (lane << 2)];
#pragma unroll
            for (int s = 0; s < NS; s++) {
                float2 v = myhs[s * Hh + i];
                bacc[s][0] = fmaf(v.x, w.x, bacc[s][0]);
                bacc[s][1] = fmaf(v.x, w.y, bacc[s][1]);
                bacc[s][2] = fmaf(v.x, w.z, bacc[s][2]);
                bacc[s][3] = fmaf(v.x, w.w, bacc[s][3]);
                racc[s][0] = fmaf(v.y, e.x, racc[s][0]);
                racc[s][1] = fmaf(v.y, e.y, racc[s][1]);
                racc[s][2] = fmaf(v.y, e.z, racc[s][2]);
                racc[s][3] = fmaf(v.y, e.w, racc[s][3]);
            }
        }

        // ---- phase C: layer 3 + trace + reduce + store ----
#pragma unroll
        for (int s = 0; s < NS; s++) {
            float od[8] = {0.f, 0.f, 0.f, 0.f, 0.f, 0.f, 0.f, 0.f};
            float tr = 0.f;
#pragma unroll
            for (int k = 0; k < 4; k++) {
                float h2 = tanhf(bacc[s][k]);
                float s2v = 1.0f - h2 * h2;
                tr = fmaf(s2v, racc[s][k], tr);
                int j = lane + 32 * k;
                float4 lo = *(const float4*)&W3s[j * 8];
                float4 hi = *(const float4*)&W3s[j * 8 + 4];
                od[0] = fmaf(h2, lo.x, od[0]);
                od[1] = fmaf(h2, lo.y, od[1]);
                od[2] = fmaf(h2, lo.z, od[2]);
                od[3] = fmaf(h2, lo.w, od[3]);
                od[4] = fmaf(h2, hi.x, od[4]);
                od[5] = fmaf(h2, hi.y, od[5]);
                od[6] = fmaf(h2, hi.z, od[6]);
                od[7] = fmaf(h2, hi.w, od[7]);
            }
#pragma unroll
            for (int off = 16; off; off >>= 1) {
#pragma unroll
                for (int m = 0; m < 8; m++)
                    od[m] += __shfl_xor_sync(0xffffffffu, od[m], off);
                tr += __shfl_xor_sync(0xffffffffu, tr, off);
            }
            if (lane == 0) {
                float* o = out + (size_t)(s0 + s) * Dd;
                float4 v0 = make_float4(od[0] + b3s[0], od[1] + b3s[1],
                                        od[2] + b3s[2], od[3] + b3s[3]);
                float4 v1 = make_float4(od[4] + b3s[4], od[5] + b3s[5],
                                        od[6] + b3s[6], od[7] + b3s[7]);
                *(float4*)o = v0;
                *(float4*)(o + 4) = v1;
                out[(size_t)B * Dd + (s0 + s)] = -tr;
            }
        }
        __syncwarp();
    }
}

extern "C" void kernel_launch(void* const* d_in, const int* in_sizes, int n_in,
                              void* d_out, int out_size) {
    const float* z  = (const float*)d_in[0];
    // d_in[1] = logp_z (unused by reference output)
    const float* t  = (const float*)d_in[2];
    const float* W1 = (const float*)d_in[3];
    const float* b1 = (const float*)d_in[4];
    const float* W2 = (const float*)d_in[5];
    const float* b2 = (const float*)d_in[6];
    const float* W3 = (const float*)d_in[7];
    const float* b3 = (const float*)d_in[8];
    float* out = (float*)d_out;
    int B = in_sizes[0] / Dd;

    cudaFuncSetAttribute(cnf_main, cudaFuncAttributeMaxDynamicSharedMemorySize,
                         SMEM_BYTES);

    prep_E<<<(Hh * Hh + 255) / 256, 256>>>(W1, W2, W3);
    cnf_main<<<NBLK, THREADS, SMEM_BYTES>>>(z, t, W1, b1, W2, b2, W3, b3, out, B);
}

// round 2
// speedup vs baseline: 1.0843x; 1.0843x over previous
#include <cuda_runtime.h>

// CNF_plain: z[B,8], t scalar; MLP 9->128->128->8 with tanh; outputs
// dz_dt [B,8] and dlogp = -trace(J) [B,1], packed as [B*8 dz | B dlogp].
//
// trace = s1^T E s2 with E = W2 .* (W1[:D,:]^T W3^T), s1=1-h1^2, s2=1-h2^2.
// E precomputed per launch by prep_E.
//
// R2: NS=8 samples/warp (weight LDS amortized 2x), float4 broadcast of
// (h,s) pairs over two inner i's, 8 warps/block.

#define Hh 128
#define Dd 8
#define NW 8           // warps per block
#define NS 8           // samples per warp per group
#define THREADS (NW * 32)
#define NBLK 152

// E in lane-permuted layout: p(i,j) = i*128 + (j&31)*4 + (j>>5)
__device__ float g_Ep[Hh * Hh];

__global__ void prep_E(const float* __restrict__ W1,
                       const float* __restrict__ W2,
                       const float* __restrict__ W3) {
    int idx = blockIdx.x * blockDim.x + threadIdx.x;   // 0..16383
    if (idx >= Hh * Hh) return;
    int i = idx >> 7, j = idx & 127;
    float c = 0.f;
#pragma unroll
    for (int d = 0; d < Dd; d++)
        c = fmaf(W1[d * Hh + i], W3[j * Dd + d], c);
    g_Ep[(i << 7) + ((j & 31) << 2) + (j >> 5)] = W2[i * Hh + j] * c;
}

// smem layout (floats):
//  hs        : NW*NS*128 float2 = 16384 floats
//  W2s       : 16384 (permuted)
//  Es        : 16384 (permuted, from g_Ep)
//  W1s       : 9*128 (permuted)
//  W3s       : 128*8
//  b1s,b2s   : 128 each
//  b3s       : 8
#define SMEM_FLOATS (16384 * 3 + 9 * 128 + 128 * 8 + 128 + 128 + 8)
#define SMEM_BYTES (SMEM_FLOATS * 4)

__global__ __launch_bounds__(THREADS, 1)
void cnf_main(const float* __restrict__ z, const float* __restrict__ tptr,
              const float* __restrict__ W1, const float* __restrict__ b1,
              const float* __restrict__ W2, const float* __restrict__ b2,
              const float* __restrict__ W3, const float* __restrict__ b3,
              float* __restrict__ out, int B) {
    extern __shared__ float smem[];
    float2* hs = (float2*)smem;                // [NW][NS][128]
    float* W2s = smem + 16384;
    float* Es  = W2s + 16384;
    float* W1s = Es + 16384;
    float* W3s = W1s + 9 * Hh;
    float* b1s = W3s + Hh * Dd;
    float* b2s = b1s + Hh;
    float* b3s = b2s + Hh;

    // ---- stage weights into SMEM ----
    for (int idx = threadIdx.x; idx < Hh * Hh; idx += THREADS) {
        int i = idx >> 7, j = idx & 127;
        int p = (i << 7) + ((j & 31) << 2) + (j >> 5);
        W2s[p]  = W2[idx];
        Es[idx] = g_Ep[idx];                   // already permuted
    }
    for (int idx = threadIdx.x; idx < 9 * Hh; idx += THREADS) {
        int i = idx >> 7, j = idx & 127;
        W1s[(i << 7) + ((j & 31) << 2) + (j >> 5)] = W1[idx];
    }
    for (int idx = threadIdx.x; idx < Hh * Dd; idx += THREADS)
        W3s[idx] = W3[idx];
    if (threadIdx.x < Hh) {
        b1s[threadIdx.x] = b1[threadIdx.x];
        b2s[threadIdx.x] = b2[threadIdx.x];
    }
    if (threadIdx.x < Dd) b3s[threadIdx.x] = b3[threadIdx.x];
    __syncthreads();

    const int wid = threadIdx.x >> 5;
    const int lane = threadIdx.x & 31;
    float2* myhs = hs + (wid * NS) * Hh;       // [NS][128]
    const float t = tptr[0];

    const int nGroups = B / NS;
    const int warpGlobal = blockIdx.x * NW + wid;
    const int totalWarps = gridDim.x * NW;

    for (int g = warpGlobal; g < nGroups; g += totalWarps) {
        const int s0 = g * NS;

        // ---- phase A: layer 1 (9 -> 128) ----
        float zreg[NS];
#pragma unroll
        for (int s = 0; s < NS; s++)
            zreg[s] = (lane < Dd) ? z[(size_t)(s0 + s) * Dd + lane] : t;

        float a[NS][4];
#pragma unroll
        for (int s = 0; s < NS; s++)
#pragma unroll
            for (int k = 0; k < 4; k++)
                a[s][k] = b1s[lane + 32 * k];

#pragma unroll
        for (int i = 0; i < 9; i++) {
            float4 w = *(const float4*)&W1s[(i << 7) + (lane << 2)];
#pragma unroll
            for (int s = 0; s < NS; s++) {
                float xi = __shfl_sync(0xffffffffu, zreg[s], i);
                a[s][0] = fmaf(xi, w.x, a[s][0]);
                a[s][1] = fmaf(xi, w.y, a[s][1]);
                a[s][2] = fmaf(xi, w.z, a[s][2]);
                a[s][3] = fmaf(xi, w.w, a[s][3]);
            }
        }

        __syncwarp();
#pragma unroll
        for (int s = 0; s < NS; s++)
#pragma unroll
            for (int k = 0; k < 4; k++) {
                float h = tanhf(a[s][k]);
                myhs[s * Hh + lane + 32 * k] = make_float2(h, 1.0f - h * h);
            }
        __syncwarp();

        // ---- phase B: fused GEMVs  b = h1@W2+b2,  r = s1@E ----
        float bacc[NS][4], racc[NS][4];
#pragma unroll
        for (int s = 0; s < NS; s++)
#pragma unroll
            for (int k = 0; k < 4; k++) {
                bacc[s][k] = b2s[lane + 32 * k];
                racc[s][k] = 0.f;
            }

        // process two i's per iteration; (h,s) pairs fetched as one
        // broadcast float4 per sample covering both i's.
#pragma unroll 4
        for (int ip = 0; ip < Hh / 2; ip++) {
            const int i0 = ip * 2;
            float4 w0 = *(const float4*)&W2s[(i0 << 7) + (lane << 2)];
            float4 e0 = *(const float4*)&Es[(i0 << 7) + (lane << 2)];
            float4 w1 = *(const float4*)&W2s[((i0 + 1) << 7) + (lane << 2)];
            float4 e1 = *(const float4*)&Es[((i0 + 1) << 7) + (lane << 2)];
#pragma unroll
            for (int s = 0; s < NS; s++) {
                float4 v = *(const float4*)&myhs[s * Hh + i0]; // h0,s0,h1,s1
                bacc[s][0] = fmaf(v.x, w0.x, bacc[s][0]);
                bacc[s][1] = fmaf(v.x, w0.y, bacc[s][1]);
                bacc[s][2] = fmaf(v.x, w0.z, bacc[s][2]);
                bacc[s][3] = fmaf(v.x, w0.w, bacc[s][3]);
                racc[s][0] = fmaf(v.y, e0.x, racc[s][0]);
                racc[s][1] = fmaf(v.y, e0.y, racc[s][1]);
                racc[s][2] = fmaf(v.y, e0.z, racc[s][2]);
                racc[s][3] = fmaf(v.y, e0.w, racc[s][3]);
                bacc[s][0] = fmaf(v.z, w1.x, bacc[s][0]);
                bacc[s][1] = fmaf(v.z, w1.y, bacc[s][1]);
                bacc[s][2] = fmaf(v.z, w1.z, bacc[s][2]);
                bacc[s][3] = fmaf(v.z, w1.w, bacc[s][3]);
                racc[s][0] = fmaf(v.w, e1.x, racc[s][0]);
                racc[s][1] = fmaf(v.w, e1.y, racc[s][1]);
                racc[s][2] = fmaf(v.w, e1.z, racc[s][2]);
                racc[s][3] = fmaf(v.w, e1.w, racc[s][3]);
            }
        }

        // ---- phase C: layer 3 + trace + reduce + store ----
#pragma unroll
        for (int s = 0; s < NS; s++) {
            float od[8] = {0.f, 0.f, 0.f, 0.f, 0.f, 0.f, 0.f, 0.f};
            float tr = 0.f;
#pragma unroll
            for (int k = 0; k < 4; k++) {
                float h2 = tanhf(bacc[s][k]);
                float s2v = 1.0f - h2 * h2;
                tr = fmaf(s2v, racc[s][k], tr);
                int j = lane + 32 * k;
                float4 lo = *(const float4*)&W3s[j * 8];
                float4 hi = *(const float4*)&W3s[j * 8 + 4];
                od[0] = fmaf(h2, lo.x, od[0]);
                od[1] = fmaf(h2, lo.y, od[1]);
                od[2] = fmaf(h2, lo.z, od[2]);
                od[3] = fmaf(h2, lo.w, od[3]);
                od[4] = fmaf(h2, hi.x, od[4]);
                od[5] = fmaf(h2, hi.y, od[5]);
                od[6] = fmaf(h2, hi.z, od[6]);
                od[7] = fmaf(h2, hi.w, od[7]);
            }
#pragma unroll
            for (int off = 16; off; off >>= 1) {
#pragma unroll
                for (int m = 0; m < 8; m++)
                    od[m] += __shfl_xor_sync(0xffffffffu, od[m], off);
                tr += __shfl_xor_sync(0xffffffffu, tr, off);
            }
            if (lane == 0) {
                float* o = out + (size_t)(s0 + s) * Dd;
                float4 v0 = make_float4(od[0] + b3s[0], od[1] + b3s[1],
                                        od[2] + b3s[2], od[3] + b3s[3]);
                float4 v1 = make_float4(od[4] + b3s[4], od[5] + b3s[5],
                                        od[6] + b3s[6], od[7] + b3s[7]);
                *(float4*)o = v0;
                *(float4*)(o + 4) = v1;
                out[(size_t)B * Dd + (s0 + s)] = -tr;
            }
        }
        __syncwarp();
    }
}

extern "C" void kernel_launch(void* const* d_in, const int* in_sizes, int n_in,
                              void* d_out, int out_size) {
    const float* z  = (const float*)d_in[0];
    // d_in[1] = logp_z (unused by reference output)
    const float* t  = (const float*)d_in[2];
    const float* W1 = (const float*)d_in[3];
    const float* b1 = (const float*)d_in[4];
    const float* W2 = (const float*)d_in[5];
    const float* b2 = (const float*)d_in[6];
    const float* W3 = (const float*)d_in[7];
    const float* b3 = (const float*)d_in[8];
    float* out = (float*)d_out;
    int B = in_sizes[0] / Dd;

    cudaFuncSetAttribute(cnf_main, cudaFuncAttributeMaxDynamicSharedMemorySize,
                         SMEM_BYTES);

    prep_E<<<(Hh * Hh + 255) / 256, 256>>>(W1, W2, W3);
    cnf_main<<<NBLK, THREADS, SMEM_BYTES>>>(z, t, W1, b1, W2, b2, W3, b3, out, B);
}